// round 13
// baseline (speedup 1.0000x reference)
#include <cuda_runtime.h>
#include <cuda_bf16.h>
#include <math.h>
#include <stdint.h>

#define TT 256
#define OBS 512
#define HID 1024
#define MSG 128

typedef unsigned long long u64;

// ---- device scratch (static; no allocations) ----
__device__ __align__(16) __nv_bfloat16 g_qh[HID * MSG];        // q' hi [m][p]
__device__ __align__(16) __nv_bfloat16 g_ql[HID * MSG];        // q' lo
__device__ __align__(16) __nv_bfloat16 g_Kh[TT * OBS * MSG];   // h hi  [t][i][p]
__device__ __align__(16) __nv_bfloat16 g_Kl[TT * OBS * MSG];   // h lo
__device__ float g_qf[HID * MSG];                              // q fp32 [m][j]
__device__ float g_c[HID];                                     // c[m] = q[m].bk
__device__ float g_x[TT * OBS];                                // normalized obs
__device__ float g_act[TT * OBS];                              // b_ih+b_hh + W_ih[:,1:]@a_t
__device__ float g_wih0[512];                                  // W_ih[:,0]

// ---- packed fp32x2 helpers ----
__device__ __forceinline__ u64 ffma2(u64 a, u64 b, u64 c) {
    u64 d; asm("fma.rn.f32x2 %0, %1, %2, %3;" : "=l"(d) : "l"(a), "l"(b), "l"(c));
    return d;
}
__device__ __forceinline__ float2 up2(u64 a) {
    float lo, hi; asm("mov.b64 {%0, %1}, %2;" : "=f"(lo), "=f"(hi) : "l"(a));
    return make_float2(lo, hi);
}

__device__ __forceinline__ float fsig(float x) {
    return 1.0f / (1.0f + __expf(-x));
}
__device__ __forceinline__ float ftanh(float x) {
    float t = __expf(-2.0f * fabsf(x));
    float r = (1.0f - t) / (1.0f + t);
    return copysignf(r, x);
}

// ---------------------------------------------------------------------------
// prep: normalize obs, action term, wih0
// ---------------------------------------------------------------------------
__global__ void prep_kernel(const float* __restrict__ obs,
                            const float* __restrict__ prev_act,
                            const float* __restrict__ in_shift,
                            const float* __restrict__ in_scale,
                            const float* __restrict__ W_ih,
                            const float* __restrict__ b_ih,
                            const float* __restrict__ b_hh) {
    int idx = blockIdx.x * blockDim.x + threadIdx.x;  // 0..131071
    int i = idx & 511;
    int t = idx >> 9;

    g_x[idx] = (obs[idx] - in_shift[i]) / (in_scale[i] + 1e-8f);

    {   // action term per (t, gate j)
        int j = i;
        float a = b_ih[j] + b_hh[j];
        const float* wr = W_ih + j * 33 + 1;
        const float* ar = prev_act + t * 32;
#pragma unroll
        for (int aa = 0; aa < 32; aa++) a = fmaf(wr[aa], ar[aa], a);
        g_act[idx] = a;
    }
    if (idx < 512) g_wih0[idx] = W_ih[idx * 33];
}

// ---------------------------------------------------------------------------
// q1: q = pos_embedding @ Wq^T + bq  (fp32, [m][j])
// ---------------------------------------------------------------------------
__global__ void q1_kernel(const float* __restrict__ pe,
                          const float* __restrict__ Wq,
                          const float* __restrict__ bq) {
    int idx = blockIdx.x * blockDim.x + threadIdx.x;  // 131072
    int m = idx >> 7, j = idx & 127;
    float acc = bq[j];
    const float* per = pe + m * 128;
    const float* wr = Wq + j * 128;
#pragma unroll 4
    for (int k = 0; k < 128; k++) acc = fmaf(per[k], wr[k], acc);
    g_qf[idx] = acc;
}

// ---------------------------------------------------------------------------
// q2: q'[m][p] = sum_j q[m][j] * Wk[j][p]  (hi/lo bf16), c[m] = q[m].bk
// ---------------------------------------------------------------------------
__global__ void q2_kernel(const float* __restrict__ Wk,
                          const float* __restrict__ bk) {
    int idx = blockIdx.x * blockDim.x + threadIdx.x;  // 131072
    int m = idx >> 7, p = idx & 127;
    const float* qf = g_qf + m * 128;
    float acc = 0.0f;
#pragma unroll 4
    for (int j = 0; j < 128; j++) acc = fmaf(qf[j], Wk[j * 128 + p], acc);

    __nv_bfloat16 hb = __float2bfloat16(acc);
    __nv_bfloat16 lb = __float2bfloat16(acc - __bfloat162float(hb));
    g_qh[idx] = hb;
    g_ql[idx] = lb;

    if (p == 0) {
        float c = 0.0f;
#pragma unroll 4
        for (int j = 0; j < 128; j++) c = fmaf(qf[j], bk[j], c);
        g_c[m] = c;
    }
}

// ---------------------------------------------------------------------------
// LSTM: 128 CTAs x 4 neurons, 1024 threads (k-split).
// kh=0: k4 0..11 smem + k4 24..27 regs -> bar.arrive(b1) (non-blocking).
// kh=1: k4 12..23 smem + k4 28..31 regs -> bar.sync(b1) -> pointwise.
// b2 = full sync (h ready). 100% smem+register resident W. (R12 measured 871us)
// ---------------------------------------------------------------------------
#define WHH_P 100
#define LSTM_SMEM ((512 * WHH_P + 4096 + 512 + 8) * (int)sizeof(float))

__global__ __launch_bounds__(1024, 1) void lstm_kernel(const float* __restrict__ W_hh) {
    extern __shared__ float sm[];
    float* Whh_s = sm;                         // 512 x WHH_P : k4 0..23 (k 0..95)
    float* gtp   = Whh_s + 512 * WHH_P;        // 4096 : [kh][n][512]
    float* h_s   = gtp + 4096;                 // 512  : [n][128]
    float* s_s   = h_s + 512;                  // 8    : double-buffered s

    int tid = threadIdx.x;                     // 0..1023
    int j  = tid & 511;
    int kh = tid >> 9;                         // warp-uniform
    int n0 = blockIdx.x * 4;

    // --- stage Whh k 0..95 (24 float4 per row) ---
    for (int f = tid; f < 512 * 24; f += 1024) {
        int row = f / 24, c4 = f - row * 24;
        *(float4*)&Whh_s[row * WHH_P + c4 * 4] =
            *(const float4*)&W_hh[row * 128 + c4 * 4];
    }
    // --- register W tail: kh=0 -> k 96..111, kh=1 -> k 112..127 ---
    ulonglong2 wtail[4];
    {
        const ulonglong2* wr =
            (const ulonglong2*)(W_hh + j * 128 + 96 + kh * 16);
#pragma unroll
        for (int i = 0; i < 4; i++) wtail[i] = wr[i];
    }

    if (tid < 512) h_s[tid] = 0.0f;
    float c_r = 0.0f;                           // used on kh=1 (pointwise) threads
    float act_r = 0.0f, wih0_r = 0.0f;          // used on kh=0 threads
    if (kh == 0) {
        act_r = g_act[j];
        wih0_r = g_wih0[j];
    }
    if (tid < 4) s_s[tid] = g_x[n0 + tid];
    __syncthreads();

    for (int t = 0; t < TT; t++) {
        const float* sb = s_s + (t & 1) * 4;

        // ================= Phase A: partial gates =================
        u64 a0 = 0, a1 = 0, a2 = 0, a3 = 0;
        {
            int kb = kh * 12;   // smem k4 base for this half
#pragma unroll
            for (int i = 0; i < 12; i++) {
                int k4 = kb + i;
                ulonglong2 wv = *(const ulonglong2*)&Whh_s[j * WHH_P + k4 * 4];
                ulonglong2 h0 = *(const ulonglong2*)&h_s[k4 * 4];
                ulonglong2 h1 = *(const ulonglong2*)&h_s[128 + k4 * 4];
                ulonglong2 h2 = *(const ulonglong2*)&h_s[256 + k4 * 4];
                ulonglong2 h3 = *(const ulonglong2*)&h_s[384 + k4 * 4];
                a0 = ffma2(wv.x, h0.x, a0); a0 = ffma2(wv.y, h0.y, a0);
                a1 = ffma2(wv.x, h1.x, a1); a1 = ffma2(wv.y, h1.y, a1);
                a2 = ffma2(wv.x, h2.x, a2); a2 = ffma2(wv.y, h2.y, a2);
                a3 = ffma2(wv.x, h3.x, a3); a3 = ffma2(wv.y, h3.y, a3);
            }
            int kt = 24 + kh * 4;  // register-tail k4 base
#pragma unroll
            for (int i = 0; i < 4; i++) {
                int k4 = kt + i;
                ulonglong2 wv = wtail[i];
                ulonglong2 h0 = *(const ulonglong2*)&h_s[k4 * 4];
                ulonglong2 h1 = *(const ulonglong2*)&h_s[128 + k4 * 4];
                ulonglong2 h2 = *(const ulonglong2*)&h_s[256 + k4 * 4];
                ulonglong2 h3 = *(const ulonglong2*)&h_s[384 + k4 * 4];
                a0 = ffma2(wv.x, h0.x, a0); a0 = ffma2(wv.y, h0.y, a0);
                a1 = ffma2(wv.x, h1.x, a1); a1 = ffma2(wv.y, h1.y, a1);
                a2 = ffma2(wv.x, h2.x, a2); a2 = ffma2(wv.y, h2.y, a2);
                a3 = ffma2(wv.x, h3.x, a3); a3 = ffma2(wv.y, h3.y, a3);
            }
        }

        if (kh == 0) {
            float2 v0 = up2(a0), v1 = up2(a1), v2 = up2(a2), v3 = up2(a3);
            gtp[0 * 512 + j] = v0.x + v0.y + fmaf(sb[0], wih0_r, act_r);
            gtp[1 * 512 + j] = v1.x + v1.y + fmaf(sb[1], wih0_r, act_r);
            gtp[2 * 512 + j] = v2.x + v2.y + fmaf(sb[2], wih0_r, act_r);
            gtp[3 * 512 + j] = v3.x + v3.y + fmaf(sb[3], wih0_r, act_r);
            // producers post their partials and DON'T block
            asm volatile("bar.arrive 1, 1024;" ::: "memory");
            // prefetch next-step inputs while consumers run pointwise
            int tn = (t + 1 < TT) ? t + 1 : t;
            if (tid < 4) s_s[((t + 1) & 1) * 4 + tid] = g_x[tn * 512 + n0 + tid];
            act_r = g_act[tn * 512 + j];
        } else {
            float2 v0 = up2(a0), v1 = up2(a1), v2 = up2(a2), v3 = up2(a3);
            gtp[2048 + 0 * 512 + j] = v0.x + v0.y;
            gtp[2048 + 1 * 512 + j] = v1.x + v1.y;
            gtp[2048 + 2 * 512 + j] = v2.x + v2.y;
            gtp[2048 + 3 * 512 + j] = v3.x + v3.y;
            // wait for producers' partials (and own group's STS)
            asm volatile("bar.sync 1, 1024;" ::: "memory");
            // pointwise (torch gate order i,f,g,o)
            int n = j >> 7, jj = j & 127;
            float ig = gtp[n * 512 + jj]        + gtp[2048 + n * 512 + jj];
            float fg = gtp[n * 512 + 128 + jj]  + gtp[2048 + n * 512 + 128 + jj];
            float gg = gtp[n * 512 + 256 + jj]  + gtp[2048 + n * 512 + 256 + jj];
            float og = gtp[n * 512 + 384 + jj]  + gtp[2048 + n * 512 + 384 + jj];
            float c = fsig(fg) * c_r + fsig(ig) * ftanh(gg);
            float h = fsig(og) * ftanh(c);
            c_r = c;
            h_s[n * 128 + jj] = h;
            __nv_bfloat16 hb = __float2bfloat16(h);
            __nv_bfloat16 lb = __float2bfloat16(h - __bfloat162float(hb));
            size_t off = (size_t)t * 65536 + (size_t)(n0 + n) * 128 + jj;
            g_Kh[off] = hb;
            g_Kl[off] = lb;
        }
        // full sync: h(t) visible to everyone
        asm volatile("bar.sync 2, 1024;" ::: "memory");
    }
}

// ---------------------------------------------------------------------------
// Attention via mma.sync m16n8k16 bf16 (hi/lo split, fp32 accumulate).
// score[m,i] = q'[m].h[t,i] + c[m];  out[t,m] = tanh(sum_i tanh(score*inv)*s)
// CTA = 64 m x 512 i, 4 chunks of 128 i, ~104KB smem -> 2 CTAs/SM.
// (R9 version, measured 399us)
// ---------------------------------------------------------------------------
#define QP 136   // smem row pitch (bf16) -> conflict-free 32-bit fragment loads
#define QTILE (64 * QP)
#define KTILE (128 * QP)
#define ATTN_SMEM ((2 * QTILE + 2 * KTILE) * 2 + 512 * 4 + 256 * 4 + 128)

__device__ __forceinline__ uint32_t lds_u32(const __nv_bfloat16* p) {
    return *(const uint32_t*)p;
}

__device__ __forceinline__ void mma_bf16(float* d, const uint32_t* a,
                                         uint32_t b0, uint32_t b1) {
    asm volatile(
        "mma.sync.aligned.m16n8k16.row.col.f32.bf16.bf16.f32 "
        "{%0,%1,%2,%3}, {%4,%5,%6,%7}, {%8,%9}, {%0,%1,%2,%3};"
        : "+f"(d[0]), "+f"(d[1]), "+f"(d[2]), "+f"(d[3])
        : "r"(a[0]), "r"(a[1]), "r"(a[2]), "r"(a[3]), "r"(b0), "r"(b1));
}

__global__ __launch_bounds__(512) void attn_kernel(float* __restrict__ out) {
    extern __shared__ char smc[];
    __nv_bfloat16* qh_s = (__nv_bfloat16*)smc;        // 64 x QP
    __nv_bfloat16* ql_s = qh_s + QTILE;
    __nv_bfloat16* Kh_s = ql_s + QTILE;               // 128 x QP
    __nv_bfloat16* Kl_s = Kh_s + KTILE;
    float* s_s  = (float*)(Kl_s + KTILE);             // 512 floats
    float* part = s_s + 512;                          // 256 floats

    int tid = threadIdx.x;
    int warp = tid >> 5;
    int lane = tid & 31;
    int wband = warp >> 2;   // 0..3 : m band (16 rows)
    int iq    = warp & 3;    // 0..3 : i quarter (32 i) within chunk
    int g  = lane >> 2;      // 0..7
    int tg = lane & 3;       // 0..3
    int m0 = wband * 16;
    int mq = blockIdx.x;     // 0..15 (64 m rows each)
    int t  = blockIdx.y;     // 0..255

    // per-thread score constants c[m] for rows m0+g, m0+g+8
    float c0 = g_c[mq * 64 + m0 + g];
    float c1 = g_c[mq * 64 + m0 + g + 8];

    // stage q' tile (hi/lo) with pitch QP
    {
        const float4* sh = (const float4*)&g_qh[(size_t)mq * 64 * 128];
        const float4* sl = (const float4*)&g_ql[(size_t)mq * 64 * 128];
        for (int f = tid; f < 1024; f += 512) {
            int row = f >> 4, qd = f & 15;
            *(float4*)&qh_s[row * QP + qd * 8] = sh[f];
            *(float4*)&ql_s[row * QP + qd * 8] = sl[f];
        }
        const float4* sx = (const float4*)&g_x[t * 512];
        if (tid < 128) ((float4*)s_s)[tid] = sx[tid];
    }

    float pr0 = 0.0f, pr1 = 0.0f;   // partials for rows m0+g, m0+g+8
    const float inv = 0.0883883476483184f;  // 1/sqrt(128)

#pragma unroll 1
    for (int c = 0; c < 4; c++) {
        if (c > 0) __syncthreads();   // everyone done with previous h tile
        {
            const float4* sh = (const float4*)&g_Kh[(size_t)t * 65536 + (size_t)c * 128 * 128];
            const float4* sl = (const float4*)&g_Kl[(size_t)t * 65536 + (size_t)c * 128 * 128];
            for (int f = tid; f < 2048; f += 512) {
                int row = f >> 4, qd = f & 15;
                *(float4*)&Kh_s[row * QP + qd * 8] = sh[f];
                *(float4*)&Kl_s[row * QP + qd * 8] = sl[f];
            }
        }
        __syncthreads();

        float acc[4][4];
#pragma unroll
        for (int nt = 0; nt < 4; nt++)
#pragma unroll
            for (int e = 0; e < 4; e++) acc[nt][e] = 0.0f;

#pragma unroll 1
        for (int kk = 0; kk < 8; kk++) {
            int ka = kk * 16 + tg * 2;
            uint32_t ah[4], al[4];
            ah[0] = lds_u32(&qh_s[(m0 + g) * QP + ka]);
            ah[1] = lds_u32(&qh_s[(m0 + g + 8) * QP + ka]);
            ah[2] = lds_u32(&qh_s[(m0 + g) * QP + ka + 8]);
            ah[3] = lds_u32(&qh_s[(m0 + g + 8) * QP + ka + 8]);
            al[0] = lds_u32(&ql_s[(m0 + g) * QP + ka]);
            al[1] = lds_u32(&ql_s[(m0 + g + 8) * QP + ka]);
            al[2] = lds_u32(&ql_s[(m0 + g) * QP + ka + 8]);
            al[3] = lds_u32(&ql_s[(m0 + g + 8) * QP + ka + 8]);
#pragma unroll
            for (int nt = 0; nt < 4; nt++) {
                int ib = (iq * 32 + nt * 8 + g) * QP + ka;
                uint32_t bh0 = lds_u32(&Kh_s[ib]);
                uint32_t bh1 = lds_u32(&Kh_s[ib + 8]);
                uint32_t bl0 = lds_u32(&Kl_s[ib]);
                uint32_t bl1 = lds_u32(&Kl_s[ib + 8]);
                mma_bf16(acc[nt], ah, bh0, bh1);   // hi*hi
                mma_bf16(acc[nt], ah, bl0, bl1);   // hi*lo
                mma_bf16(acc[nt], al, bh0, bh1);   // lo*hi
            }
        }

        // epilogue for this chunk: tanh((score + c[m]) * inv) * s[i]
#pragma unroll
        for (int nt = 0; nt < 4; nt++) {
            int i0 = c * 128 + iq * 32 + nt * 8 + tg * 2;
            float sv0 = s_s[i0], sv1 = s_s[i0 + 1];
            pr0 = fmaf(ftanh((acc[nt][0] + c0) * inv), sv0, pr0);
            pr0 = fmaf(ftanh((acc[nt][1] + c0) * inv), sv1, pr0);
            pr1 = fmaf(ftanh((acc[nt][2] + c1) * inv), sv0, pr1);
            pr1 = fmaf(ftanh((acc[nt][3] + c1) * inv), sv1, pr1);
        }
    }

    // reduce over the 4 tg lanes, then across i-quarters via smem
    pr0 += __shfl_xor_sync(0xffffffffu, pr0, 1);
    pr0 += __shfl_xor_sync(0xffffffffu, pr0, 2);
    pr1 += __shfl_xor_sync(0xffffffffu, pr1, 1);
    pr1 += __shfl_xor_sync(0xffffffffu, pr1, 2);
    if (tg == 0) {
        part[iq * 64 + m0 + g]     = pr0;
        part[iq * 64 + m0 + g + 8] = pr1;
    }
    __syncthreads();
    if (tid < 64)
        out[t * 1024 + mq * 64 + tid] =
            ftanh(part[tid] + part[64 + tid] + part[128 + tid] + part[192 + tid]);
}

// ---------------------------------------------------------------------------
extern "C" void kernel_launch(void* const* d_in, const int* in_sizes, int n_in,
                              void* d_out, int out_size) {
    const float* obs      = (const float*)d_in[0];
    const float* prev_act = (const float*)d_in[1];
    const float* in_shift = (const float*)d_in[2];
    const float* in_scale = (const float*)d_in[3];
    const float* pe       = (const float*)d_in[4];
    const float* W_ih     = (const float*)d_in[5];
    const float* b_ih     = (const float*)d_in[6];
    const float* W_hh     = (const float*)d_in[7];
    const float* b_hh     = (const float*)d_in[8];
    const float* Wq       = (const float*)d_in[9];
    const float* bq       = (const float*)d_in[10];
    const float* Wk       = (const float*)d_in[11];
    const float* bk       = (const float*)d_in[12];
    float* out = (float*)d_out;

    cudaFuncSetAttribute(attn_kernel, cudaFuncAttributeMaxDynamicSharedMemorySize,
                         ATTN_SMEM);
    cudaFuncSetAttribute(lstm_kernel, cudaFuncAttributeMaxDynamicSharedMemorySize,
                         LSTM_SMEM);

    prep_kernel<<<512, 256>>>(obs, prev_act, in_shift, in_scale, W_ih, b_ih, b_hh);
    q1_kernel<<<512, 256>>>(pe, Wq, bq);
    q2_kernel<<<512, 256>>>(Wk, bk);
    lstm_kernel<<<128, 1024, LSTM_SMEM>>>(W_hh);
    dim3 ga(16, 256);
    attn_kernel<<<ga, 512, ATTN_SMEM>>>(out);
}

// round 14
// speedup vs baseline: 1.6204x; 1.6204x over previous
#include <cuda_runtime.h>
#include <cuda_bf16.h>
#include <math.h>
#include <stdint.h>

#define TT 256
#define OBS 512
#define HID 1024
#define MSG 128

typedef unsigned long long u64;

// ---- device scratch (static; no allocations) ----
__device__ __align__(16) __nv_bfloat16 g_qh[HID * MSG];        // q' hi [m][p]
__device__ __align__(16) __nv_bfloat16 g_ql[HID * MSG];        // q' lo
__device__ __align__(16) __nv_bfloat16 g_Kh[TT * OBS * MSG];   // h hi  [t][i][p]
__device__ __align__(16) __nv_bfloat16 g_Kl[TT * OBS * MSG];   // h lo
__device__ float g_qf[HID * MSG];                              // q fp32 [m][j]
__device__ float g_c[HID];                                     // c[m] = q[m].bk
__device__ float g_x[TT * OBS];                                // normalized obs
__device__ float g_act[TT * OBS];                              // b_ih+b_hh + W_ih[:,1:]@a_t
__device__ float g_wih0[512];                                  // W_ih[:,0]
// W_hh as MMA fragment-linear images: [(mtw*8+kt)*32 + lane] -> uint4 (4 frag regs)
__device__ __align__(16) uint4 g_WhiF[8192];                   // 128 KB
__device__ __align__(16) uint4 g_WloF[8192];                   // 128 KB

__device__ __forceinline__ float fsig(float x) {
    return 1.0f / (1.0f + __expf(-x));
}
__device__ __forceinline__ float ftanh(float x) {
    float t = __expf(-2.0f * fabsf(x));
    float r = (1.0f - t) / (1.0f + t);
    return copysignf(r, x);
}

__device__ __forceinline__ void mma_bf16(float* d, const uint32_t* a,
                                         uint32_t b0, uint32_t b1) {
    asm volatile(
        "mma.sync.aligned.m16n8k16.row.col.f32.bf16.bf16.f32 "
        "{%0,%1,%2,%3}, {%4,%5,%6,%7}, {%8,%9}, {%0,%1,%2,%3};"
        : "+f"(d[0]), "+f"(d[1]), "+f"(d[2]), "+f"(d[3])
        : "r"(a[0]), "r"(a[1]), "r"(a[2]), "r"(a[3]), "r"(b0), "r"(b1));
}

// ---------------------------------------------------------------------------
// prep: normalize obs, action term, wih0
// ---------------------------------------------------------------------------
__global__ void prep_kernel(const float* __restrict__ obs,
                            const float* __restrict__ prev_act,
                            const float* __restrict__ in_shift,
                            const float* __restrict__ in_scale,
                            const float* __restrict__ W_ih,
                            const float* __restrict__ b_ih,
                            const float* __restrict__ b_hh) {
    int idx = blockIdx.x * blockDim.x + threadIdx.x;  // 0..131071
    int i = idx & 511;
    int t = idx >> 9;

    g_x[idx] = (obs[idx] - in_shift[i]) / (in_scale[i] + 1e-8f);

    {   // action term per (t, gate j)
        int j = i;
        float a = b_ih[j] + b_hh[j];
        const float* wr = W_ih + j * 33 + 1;
        const float* ar = prev_act + t * 32;
#pragma unroll
        for (int aa = 0; aa < 32; aa++) a = fmaf(wr[aa], ar[aa], a);
        g_act[idx] = a;
    }
    if (idx < 512) g_wih0[idx] = W_ih[idx * 33];
}

// ---------------------------------------------------------------------------
// wfrag: pack W_hh into m16n8k16 A-fragment-linear hi/lo images.
// tile id = mtw*8 + kt (mtw = warp*2 + mtile, 0..31); per lane 4 regs:
// r0:(g, k0) r1:(g+8, k0) r2:(g, k0+8) r3:(g+8, k0+8), each reg = 2 bf16 (k,k+1)
// ---------------------------------------------------------------------------
__global__ void wfrag_kernel(const float* __restrict__ W_hh) {
    int idx = blockIdx.x * blockDim.x + threadIdx.x;   // 0..8191
    int lane = idx & 31;
    int tile = idx >> 5;
    int kt = tile & 7;
    int mtw = tile >> 3;
    int g = lane >> 2, tg = lane & 3;
    int jb = mtw * 16;
    int k0 = kt * 16 + tg * 2;

    uint32_t hi[4], lo[4];
#pragma unroll
    for (int r = 0; r < 4; r++) {
        int row = jb + g + (r & 1) * 8;
        int col = k0 + (r >> 1) * 8;
        float w0 = W_hh[row * 128 + col];
        float w1 = W_hh[row * 128 + col + 1];
        __nv_bfloat16 h0 = __float2bfloat16(w0);
        __nv_bfloat16 h1 = __float2bfloat16(w1);
        __nv_bfloat16 l0 = __float2bfloat16(w0 - __bfloat162float(h0));
        __nv_bfloat16 l1 = __float2bfloat16(w1 - __bfloat162float(h1));
        hi[r] = (uint32_t)*(uint16_t*)&h0 | ((uint32_t)*(uint16_t*)&h1 << 16);
        lo[r] = (uint32_t)*(uint16_t*)&l0 | ((uint32_t)*(uint16_t*)&l1 << 16);
    }
    g_WhiF[idx] = make_uint4(hi[0], hi[1], hi[2], hi[3]);
    g_WloF[idx] = make_uint4(lo[0], lo[1], lo[2], lo[3]);
}

// ---------------------------------------------------------------------------
// q1: q = pos_embedding @ Wq^T + bq  (fp32, [m][j])
// ---------------------------------------------------------------------------
__global__ void q1_kernel(const float* __restrict__ pe,
                          const float* __restrict__ Wq,
                          const float* __restrict__ bq) {
    int idx = blockIdx.x * blockDim.x + threadIdx.x;  // 131072
    int m = idx >> 7, j = idx & 127;
    float acc = bq[j];
    const float* per = pe + m * 128;
    const float* wr = Wq + j * 128;
#pragma unroll 4
    for (int k = 0; k < 128; k++) acc = fmaf(per[k], wr[k], acc);
    g_qf[idx] = acc;
}

// ---------------------------------------------------------------------------
// q2: q'[m][p] = sum_j q[m][j] * Wk[j][p]  (hi/lo bf16), c[m] = q[m].bk
// ---------------------------------------------------------------------------
__global__ void q2_kernel(const float* __restrict__ Wk,
                          const float* __restrict__ bk) {
    int idx = blockIdx.x * blockDim.x + threadIdx.x;  // 131072
    int m = idx >> 7, p = idx & 127;
    const float* qf = g_qf + m * 128;
    float acc = 0.0f;
#pragma unroll 4
    for (int j = 0; j < 128; j++) acc = fmaf(qf[j], Wk[j * 128 + p], acc);

    __nv_bfloat16 hb = __float2bfloat16(acc);
    __nv_bfloat16 lb = __float2bfloat16(acc - __bfloat162float(hb));
    g_qh[idx] = hb;
    g_ql[idx] = lb;

    if (p == 0) {
        float c = 0.0f;
#pragma unroll 4
        for (int j = 0; j < 128; j++) c = fmaf(qf[j], bk[j], c);
        g_c[m] = c;
    }
}

// ---------------------------------------------------------------------------
// LSTM via HMMA gate GEMM: 128 CTAs x 4 neurons, 512 threads (16 warps).
// gates[512j, 4n] = W_hh @ h^T : warp owns 32 j rows; W_hi in 64 regs,
// W_lo via smem fragment LDS.128; h as bf16 hi/lo [n(8 pad)][k] rows.
// 48 HMMA/warp/step; pointwise on all 512 threads; 2 barriers/step.
// ---------------------------------------------------------------------------
#define GTP 516
#define WLO_B 0
#define GT_B  131072
#define HHI_B (GT_B + 8320)
#define HLO_B (HHI_B + 2176)
#define ACT_B (HLO_B + 2176)
#define WIH_B (ACT_B + 4096)
#define SS_B  (WIH_B + 2048)
#define LSTM_SMEM (SS_B + 32)

__global__ __launch_bounds__(512, 1) void lstm_kernel() {
    extern __shared__ char smc[];
    uint4* wlo_s = (uint4*)(smc + WLO_B);             // 8192 uint4
    float* gt_s  = (float*)(smc + GT_B);              // 4 x GTP
    __nv_bfloat16* hhi = (__nv_bfloat16*)(smc + HHI_B);  // 8 x 136
    __nv_bfloat16* hlo = (__nv_bfloat16*)(smc + HLO_B);
    float* act_s = (float*)(smc + ACT_B);             // 2 x 512
    float* wih_s = (float*)(smc + WIH_B);             // 512
    float* s_s   = (float*)(smc + SS_B);              // 2 x 4

    int tid = threadIdx.x;                            // 0..511
    int lane = tid & 31, w = tid >> 5;
    int g = lane >> 2, tg = lane & 3;
    int n0 = blockIdx.x * 4;
    int pn = tid >> 7, pj = tid & 127;                // pointwise mapping

    // one-time staging
#pragma unroll
    for (int f = 0; f < 16; f++) wlo_s[tid + f * 512] = g_WloF[tid + f * 512];
    uint4 whi[16];
#pragma unroll
    for (int mt = 0; mt < 2; mt++)
#pragma unroll
        for (int kt = 0; kt < 8; kt++)
            whi[mt * 8 + kt] = g_WhiF[((w * 2 + mt) * 8 + kt) * 32 + lane];
    for (int f = tid; f < 8 * 136; f += 512) { hhi[f] = __float2bfloat16(0.f); hlo[f] = __float2bfloat16(0.f); }
    wih_s[tid] = g_wih0[tid];
    act_s[tid] = g_act[tid];
    if (tid < 4) s_s[tid] = g_x[n0 + tid];
    float c_r = 0.0f;
    __syncthreads();

    for (int t = 0; t < TT; t++) {
        // prefetch next-step inputs into regs (overlaps MMA phase)
        int tn = (t + 1 < TT) ? t + 1 : t;
        float act_n = g_act[tn * 512 + tid];
        float s_n = (tid < 4) ? g_x[tn * 512 + n0 + tid] : 0.0f;

        // ---- gate GEMM: D[j 32][n 8] per warp, K=128 over 8 ktiles ----
        float acc0[4] = {0, 0, 0, 0};
        float acc1[4] = {0, 0, 0, 0};
#pragma unroll
        for (int kt = 0; kt < 8; kt++) {
            int ka = kt * 16 + tg * 2;
            uint32_t bh0 = *(const uint32_t*)&hhi[g * 136 + ka];
            uint32_t bh1 = *(const uint32_t*)&hhi[g * 136 + ka + 8];
            uint32_t bl0 = *(const uint32_t*)&hlo[g * 136 + ka];
            uint32_t bl1 = *(const uint32_t*)&hlo[g * 136 + ka + 8];
            {
                uint4 wv = whi[kt];
                uint32_t a[4] = {wv.x, wv.y, wv.z, wv.w};
                mma_bf16(acc0, a, bh0, bh1);
                mma_bf16(acc0, a, bl0, bl1);
                uint4 wl = wlo_s[((w * 2 + 0) * 8 + kt) * 32 + lane];
                uint32_t al[4] = {wl.x, wl.y, wl.z, wl.w};
                mma_bf16(acc0, al, bh0, bh1);
            }
            {
                uint4 wv = whi[8 + kt];
                uint32_t a[4] = {wv.x, wv.y, wv.z, wv.w};
                mma_bf16(acc1, a, bh0, bh1);
                mma_bf16(acc1, a, bl0, bl1);
                uint4 wl = wlo_s[((w * 2 + 1) * 8 + kt) * 32 + lane];
                uint32_t al[4] = {wl.x, wl.y, wl.z, wl.w};
                mma_bf16(acc1, al, bh0, bh1);
            }
        }
        // store D -> gt_s (only tg<2 hold valid neuron cols 0..3)
        if (tg < 2) {
            int j0 = w * 32 + g;
            gt_s[(tg * 2) * GTP + j0]          = acc0[0];
            gt_s[(tg * 2 + 1) * GTP + j0]      = acc0[1];
            gt_s[(tg * 2) * GTP + j0 + 8]      = acc0[2];
            gt_s[(tg * 2 + 1) * GTP + j0 + 8]  = acc0[3];
            int j1 = j0 + 16;
            gt_s[(tg * 2) * GTP + j1]          = acc1[0];
            gt_s[(tg * 2 + 1) * GTP + j1]      = acc1[1];
            gt_s[(tg * 2) * GTP + j1 + 8]      = acc1[2];
            gt_s[(tg * 2 + 1) * GTP + j1 + 8]  = acc1[3];
        }
        // stash prefetched inputs (buffer (t+1)&1; read buffer is (t)&1)
        act_s[((t + 1) & 1) * 512 + tid] = act_n;
        if (tid < 4) s_s[((t + 1) & 1) * 4 + tid] = s_n;
        __syncthreads();

        // ---- pointwise: thread = (pn, pj); torch gate order i,f,g,o ----
        {
            const float* ab = act_s + (t & 1) * 512;
            float sv = s_s[(t & 1) * 4 + pn];
            float gv[4];
#pragma unroll
            for (int e = 0; e < 4; e++) {
                int gi = e * 128 + pj;
                gv[e] = gt_s[pn * GTP + gi] + ab[gi] + sv * wih_s[gi];
            }
            float c = fsig(gv[1]) * c_r + fsig(gv[0]) * ftanh(gv[2]);
            float h = fsig(gv[3]) * ftanh(c);
            c_r = c;
            __nv_bfloat16 hb = __float2bfloat16(h);
            __nv_bfloat16 lb = __float2bfloat16(h - __bfloat162float(hb));
            hhi[pn * 136 + pj] = hb;
            hlo[pn * 136 + pj] = lb;
            size_t off = (size_t)t * 65536 + (size_t)(n0 + pn) * 128 + pj;
            g_Kh[off] = hb;
            g_Kl[off] = lb;
        }
        __syncthreads();
    }
}

// ---------------------------------------------------------------------------
// Attention via mma.sync m16n8k16 bf16 (hi/lo split, fp32 accumulate).
// score[m,i] = q'[m].h[t,i] + c[m];  out[t,m] = tanh(sum_i tanh(score*inv)*s)
// CTA = 64 m x 512 i, 4 chunks of 128 i, ~104KB smem -> 2 CTAs/SM.
// (R9 version, measured 399us)
// ---------------------------------------------------------------------------
#define QP 136   // smem row pitch (bf16) -> conflict-free 32-bit fragment loads
#define QTILE (64 * QP)
#define KTILE (128 * QP)
#define ATTN_SMEM ((2 * QTILE + 2 * KTILE) * 2 + 512 * 4 + 256 * 4 + 128)

__device__ __forceinline__ uint32_t lds_u32(const __nv_bfloat16* p) {
    return *(const uint32_t*)p;
}

__global__ __launch_bounds__(512) void attn_kernel(float* __restrict__ out) {
    extern __shared__ char smc[];
    __nv_bfloat16* qh_s = (__nv_bfloat16*)smc;        // 64 x QP
    __nv_bfloat16* ql_s = qh_s + QTILE;
    __nv_bfloat16* Kh_s = ql_s + QTILE;               // 128 x QP
    __nv_bfloat16* Kl_s = Kh_s + KTILE;
    float* s_s  = (float*)(Kl_s + KTILE);             // 512 floats
    float* part = s_s + 512;                          // 256 floats

    int tid = threadIdx.x;
    int warp = tid >> 5;
    int lane = tid & 31;
    int wband = warp >> 2;   // 0..3 : m band (16 rows)
    int iq    = warp & 3;    // 0..3 : i quarter (32 i) within chunk
    int g  = lane >> 2;      // 0..7
    int tg = lane & 3;       // 0..3
    int m0 = wband * 16;
    int mq = blockIdx.x;     // 0..15 (64 m rows each)
    int t  = blockIdx.y;     // 0..255

    float c0 = g_c[mq * 64 + m0 + g];
    float c1 = g_c[mq * 64 + m0 + g + 8];

    {
        const float4* sh = (const float4*)&g_qh[(size_t)mq * 64 * 128];
        const float4* sl = (const float4*)&g_ql[(size_t)mq * 64 * 128];
        for (int f = tid; f < 1024; f += 512) {
            int row = f >> 4, qd = f & 15;
            *(float4*)&qh_s[row * QP + qd * 8] = sh[f];
            *(float4*)&ql_s[row * QP + qd * 8] = sl[f];
        }
        const float4* sx = (const float4*)&g_x[t * 512];
        if (tid < 128) ((float4*)s_s)[tid] = sx[tid];
    }

    float pr0 = 0.0f, pr1 = 0.0f;
    const float inv = 0.0883883476483184f;  // 1/sqrt(128)

#pragma unroll 1
    for (int c = 0; c < 4; c++) {
        if (c > 0) __syncthreads();
        {
            const float4* sh = (const float4*)&g_Kh[(size_t)t * 65536 + (size_t)c * 128 * 128];
            const float4* sl = (const float4*)&g_Kl[(size_t)t * 65536 + (size_t)c * 128 * 128];
            for (int f = tid; f < 2048; f += 512) {
                int row = f >> 4, qd = f & 15;
                *(float4*)&Kh_s[row * QP + qd * 8] = sh[f];
                *(float4*)&Kl_s[row * QP + qd * 8] = sl[f];
            }
        }
        __syncthreads();

        float acc[4][4];
#pragma unroll
        for (int nt = 0; nt < 4; nt++)
#pragma unroll
            for (int e = 0; e < 4; e++) acc[nt][e] = 0.0f;

#pragma unroll 1
        for (int kk = 0; kk < 8; kk++) {
            int ka = kk * 16 + tg * 2;
            uint32_t ah[4], al[4];
            ah[0] = lds_u32(&qh_s[(m0 + g) * QP + ka]);
            ah[1] = lds_u32(&qh_s[(m0 + g + 8) * QP + ka]);
            ah[2] = lds_u32(&qh_s[(m0 + g) * QP + ka + 8]);
            ah[3] = lds_u32(&qh_s[(m0 + g + 8) * QP + ka + 8]);
            al[0] = lds_u32(&ql_s[(m0 + g) * QP + ka]);
            al[1] = lds_u32(&ql_s[(m0 + g + 8) * QP + ka]);
            al[2] = lds_u32(&ql_s[(m0 + g) * QP + ka + 8]);
            al[3] = lds_u32(&ql_s[(m0 + g + 8) * QP + ka + 8]);
#pragma unroll
            for (int nt = 0; nt < 4; nt++) {
                int ib = (iq * 32 + nt * 8 + g) * QP + ka;
                uint32_t bh0 = lds_u32(&Kh_s[ib]);
                uint32_t bh1 = lds_u32(&Kh_s[ib + 8]);
                uint32_t bl0 = lds_u32(&Kl_s[ib]);
                uint32_t bl1 = lds_u32(&Kl_s[ib + 8]);
                mma_bf16(acc[nt], ah, bh0, bh1);   // hi*hi
                mma_bf16(acc[nt], ah, bl0, bl1);   // hi*lo
                mma_bf16(acc[nt], al, bh0, bh1);   // lo*hi
            }
        }

#pragma unroll
        for (int nt = 0; nt < 4; nt++) {
            int i0 = c * 128 + iq * 32 + nt * 8 + tg * 2;
            float sv0 = s_s[i0], sv1 = s_s[i0 + 1];
            pr0 = fmaf(ftanh((acc[nt][0] + c0) * inv), sv0, pr0);
            pr0 = fmaf(ftanh((acc[nt][1] + c0) * inv), sv1, pr0);
            pr1 = fmaf(ftanh((acc[nt][2] + c1) * inv), sv0, pr1);
            pr1 = fmaf(ftanh((acc[nt][3] + c1) * inv), sv1, pr1);
        }
    }

    pr0 += __shfl_xor_sync(0xffffffffu, pr0, 1);
    pr0 += __shfl_xor_sync(0xffffffffu, pr0, 2);
    pr1 += __shfl_xor_sync(0xffffffffu, pr1, 1);
    pr1 += __shfl_xor_sync(0xffffffffu, pr1, 2);
    if (tg == 0) {
        part[iq * 64 + m0 + g]     = pr0;
        part[iq * 64 + m0 + g + 8] = pr1;
    }
    __syncthreads();
    if (tid < 64)
        out[t * 1024 + mq * 64 + tid] =
            ftanh(part[tid] + part[64 + tid] + part[128 + tid] + part[192 + tid]);
}

// ---------------------------------------------------------------------------
extern "C" void kernel_launch(void* const* d_in, const int* in_sizes, int n_in,
                              void* d_out, int out_size) {
    const float* obs      = (const float*)d_in[0];
    const float* prev_act = (const float*)d_in[1];
    const float* in_shift = (const float*)d_in[2];
    const float* in_scale = (const float*)d_in[3];
    const float* pe       = (const float*)d_in[4];
    const float* W_ih     = (const float*)d_in[5];
    const float* b_ih     = (const float*)d_in[6];
    const float* W_hh     = (const float*)d_in[7];
    const float* b_hh     = (const float*)d_in[8];
    const float* Wq       = (const float*)d_in[9];
    const float* bq       = (const float*)d_in[10];
    const float* Wk       = (const float*)d_in[11];
    const float* bk       = (const float*)d_in[12];
    float* out = (float*)d_out;

    cudaFuncSetAttribute(attn_kernel, cudaFuncAttributeMaxDynamicSharedMemorySize,
                         ATTN_SMEM);
    cudaFuncSetAttribute(lstm_kernel, cudaFuncAttributeMaxDynamicSharedMemorySize,
                         LSTM_SMEM);

    prep_kernel<<<512, 256>>>(obs, prev_act, in_shift, in_scale, W_ih, b_ih, b_hh);
    wfrag_kernel<<<32, 256>>>(W_hh);
    q1_kernel<<<512, 256>>>(pe, Wq, bq);
    q2_kernel<<<512, 256>>>(Wk, bk);
    lstm_kernel<<<128, 512, LSTM_SMEM>>>();
    dim3 ga(16, 256);
    attn_kernel<<<ga, 512, ATTN_SMEM>>>(out);
}

// round 15
// speedup vs baseline: 1.6663x; 1.0283x over previous
#include <cuda_runtime.h>
#include <cuda_bf16.h>
#include <math.h>
#include <stdint.h>

#define TT 256
#define OBS 512
#define HID 1024
#define MSG 128

typedef unsigned long long u64;

// ---- device scratch (static; no allocations) ----
// q' as A-fragment-linear: tile(16m x 16k) id = mt*8+kt, 256 bf16/tile
__device__ __align__(16) __nv_bfloat16 g_qh[HID * MSG];
__device__ __align__(16) __nv_bfloat16 g_ql[HID * MSG];
// h as B-fragment-linear per t: tile(8i x 16k) id = it*8+kt, 128 bf16/tile
__device__ __align__(16) __nv_bfloat16 g_Kh[TT * OBS * MSG];
__device__ __align__(16) __nv_bfloat16 g_Kl[TT * OBS * MSG];
__device__ float g_qf[HID * MSG];                              // q fp32 [m][j]
__device__ float g_c[HID];                                     // c[m] = q[m].bk
__device__ float g_x[TT * OBS];                                // normalized obs
__device__ float g_act[TT * OBS];                              // b_ih+b_hh + W_ih[:,1:]@a_t
__device__ float g_wih0[512];                                  // W_ih[:,0]
// W_hh as MMA A-fragment-linear images: [(mtw*8+kt)*32 + lane] -> uint4
__device__ __align__(16) uint4 g_WhiF[8192];                   // 128 KB
__device__ __align__(16) uint4 g_WloF[8192];                   // 128 KB

__device__ __forceinline__ float fsig(float x) {
    return 1.0f / (1.0f + __expf(-x));
}
__device__ __forceinline__ float ftanh(float x) {
    float t = __expf(-2.0f * fabsf(x));
    float r = (1.0f - t) / (1.0f + t);
    return copysignf(r, x);
}

__device__ __forceinline__ void mma_bf16(float* d, const uint32_t* a,
                                         uint32_t b0, uint32_t b1) {
    asm volatile(
        "mma.sync.aligned.m16n8k16.row.col.f32.bf16.bf16.f32 "
        "{%0,%1,%2,%3}, {%4,%5,%6,%7}, {%8,%9}, {%0,%1,%2,%3};"
        : "+f"(d[0]), "+f"(d[1]), "+f"(d[2]), "+f"(d[3])
        : "r"(a[0]), "r"(a[1]), "r"(a[2]), "r"(a[3]), "r"(b0), "r"(b1));
}

// ---------------------------------------------------------------------------
// prep: normalize obs, action term, wih0
// ---------------------------------------------------------------------------
__global__ void prep_kernel(const float* __restrict__ obs,
                            const float* __restrict__ prev_act,
                            const float* __restrict__ in_shift,
                            const float* __restrict__ in_scale,
                            const float* __restrict__ W_ih,
                            const float* __restrict__ b_ih,
                            const float* __restrict__ b_hh) {
    int idx = blockIdx.x * blockDim.x + threadIdx.x;  // 0..131071
    int i = idx & 511;
    int t = idx >> 9;

    g_x[idx] = (obs[idx] - in_shift[i]) / (in_scale[i] + 1e-8f);

    {   // action term per (t, gate j)
        int j = i;
        float a = b_ih[j] + b_hh[j];
        const float* wr = W_ih + j * 33 + 1;
        const float* ar = prev_act + t * 32;
#pragma unroll
        for (int aa = 0; aa < 32; aa++) a = fmaf(wr[aa], ar[aa], a);
        g_act[idx] = a;
    }
    if (idx < 512) g_wih0[idx] = W_ih[idx * 33];
}

// ---------------------------------------------------------------------------
// wfrag: pack W_hh into m16n8k16 A-fragment-linear hi/lo images.
// ---------------------------------------------------------------------------
__global__ void wfrag_kernel(const float* __restrict__ W_hh) {
    int idx = blockIdx.x * blockDim.x + threadIdx.x;   // 0..8191
    int lane = idx & 31;
    int tile = idx >> 5;
    int kt = tile & 7;
    int mtw = tile >> 3;
    int g = lane >> 2, tg = lane & 3;
    int jb = mtw * 16;
    int k0 = kt * 16 + tg * 2;

    uint32_t hi[4], lo[4];
#pragma unroll
    for (int r = 0; r < 4; r++) {
        int row = jb + g + (r & 1) * 8;
        int col = k0 + (r >> 1) * 8;
        float w0 = W_hh[row * 128 + col];
        float w1 = W_hh[row * 128 + col + 1];
        __nv_bfloat16 h0 = __float2bfloat16(w0);
        __nv_bfloat16 h1 = __float2bfloat16(w1);
        __nv_bfloat16 l0 = __float2bfloat16(w0 - __bfloat162float(h0));
        __nv_bfloat16 l1 = __float2bfloat16(w1 - __bfloat162float(h1));
        hi[r] = (uint32_t)*(uint16_t*)&h0 | ((uint32_t)*(uint16_t*)&h1 << 16);
        lo[r] = (uint32_t)*(uint16_t*)&l0 | ((uint32_t)*(uint16_t*)&l1 << 16);
    }
    g_WhiF[idx] = make_uint4(hi[0], hi[1], hi[2], hi[3]);
    g_WloF[idx] = make_uint4(lo[0], lo[1], lo[2], lo[3]);
}

// ---------------------------------------------------------------------------
// q1: q = pos_embedding @ Wq^T + bq  (fp32, [m][j])
// ---------------------------------------------------------------------------
__global__ void q1_kernel(const float* __restrict__ pe,
                          const float* __restrict__ Wq,
                          const float* __restrict__ bq) {
    int idx = blockIdx.x * blockDim.x + threadIdx.x;  // 131072
    int m = idx >> 7, j = idx & 127;
    float acc = bq[j];
    const float* per = pe + m * 128;
    const float* wr = Wq + j * 128;
#pragma unroll 4
    for (int k = 0; k < 128; k++) acc = fmaf(per[k], wr[k], acc);
    g_qf[idx] = acc;
}

// ---------------------------------------------------------------------------
// q2: q'[m][p] -> A-fragment-linear hi/lo; c[m] = q[m].bk
// A-frag addr: tile(mt*8+kt)*256 + lane*8 + r*2 + hw
//   lane = (m&7)*4 + ((p>>1)&3), r = ((m>>3)&1) + 2*((p>>3)&1), hw = p&1
// ---------------------------------------------------------------------------
__global__ void q2_kernel(const float* __restrict__ Wk,
                          const float* __restrict__ bk) {
    int idx = blockIdx.x * blockDim.x + threadIdx.x;  // 131072
    int m = idx >> 7, p = idx & 127;
    const float* qf = g_qf + m * 128;
    float acc = 0.0f;
#pragma unroll 4
    for (int j = 0; j < 128; j++) acc = fmaf(qf[j], Wk[j * 128 + p], acc);

    __nv_bfloat16 hb = __float2bfloat16(acc);
    __nv_bfloat16 lb = __float2bfloat16(acc - __bfloat162float(hb));
    {
        int mt = m >> 4, mloc = m & 15;
        int kt = p >> 4, kloc = p & 15;
        int lane = (mloc & 7) * 4 + ((kloc >> 1) & 3);
        int r = (mloc >> 3) + 2 * (kloc >> 3);
        int a = ((mt * 8 + kt) << 8) + lane * 8 + r * 2 + (kloc & 1);
        g_qh[a] = hb;
        g_ql[a] = lb;
    }

    if (p == 0) {
        float c = 0.0f;
#pragma unroll 4
        for (int j = 0; j < 128; j++) c = fmaf(qf[j], bk[j], c);
        g_c[m] = c;
    }
}

// ---------------------------------------------------------------------------
// LSTM via HMMA gate GEMM: 128 CTAs x 4 neurons, 512 threads (16 warps).
// Writes h as B-fragment-linear g_Kh/g_Kl.
// ---------------------------------------------------------------------------
#define GTP 516
#define WLO_B 0
#define GT_B  131072
#define HHI_B (GT_B + 8320)
#define HLO_B (HHI_B + 2176)
#define ACT_B (HLO_B + 2176)
#define WIH_B (ACT_B + 4096)
#define SS_B  (WIH_B + 2048)
#define LSTM_SMEM (SS_B + 32)

__global__ __launch_bounds__(512, 1) void lstm_kernel() {
    extern __shared__ char smc[];
    uint4* wlo_s = (uint4*)(smc + WLO_B);                // 8192 uint4
    float* gt_s  = (float*)(smc + GT_B);                 // 4 x GTP
    __nv_bfloat16* hhi = (__nv_bfloat16*)(smc + HHI_B);  // 8 x 136
    __nv_bfloat16* hlo = (__nv_bfloat16*)(smc + HLO_B);
    float* act_s = (float*)(smc + ACT_B);                // 2 x 512
    float* wih_s = (float*)(smc + WIH_B);                // 512
    float* s_s   = (float*)(smc + SS_B);                 // 2 x 4

    int tid = threadIdx.x;                               // 0..511
    int lane = tid & 31, w = tid >> 5;
    int g = lane >> 2, tg = lane & 3;
    int n0 = blockIdx.x * 4;
    int pn = tid >> 7, pj = tid & 127;                   // pointwise mapping

    // one-time staging
#pragma unroll
    for (int f = 0; f < 16; f++) wlo_s[tid + f * 512] = g_WloF[tid + f * 512];
    uint4 whi[16];
#pragma unroll
    for (int mt = 0; mt < 2; mt++)
#pragma unroll
        for (int kt = 0; kt < 8; kt++)
            whi[mt * 8 + kt] = g_WhiF[((w * 2 + mt) * 8 + kt) * 32 + lane];
    for (int f = tid; f < 8 * 136; f += 512) { hhi[f] = __float2bfloat16(0.f); hlo[f] = __float2bfloat16(0.f); }
    wih_s[tid] = g_wih0[tid];
    act_s[tid] = g_act[tid];
    if (tid < 4) s_s[tid] = g_x[n0 + tid];
    float c_r = 0.0f;

    // precompute this thread's fragment-linear write address pieces
    int w_it = (n0 + pn) >> 3;
    int w_kt = pj >> 4;
    int w_kloc = pj & 15;
    int w_lane = ((n0 + pn) & 7) * 4 + ((w_kloc >> 1) & 3);
    int w_off = ((w_it * 8 + w_kt) << 7) + w_lane * 4 + (w_kloc >> 3) * 2 + (w_kloc & 1);
    __syncthreads();

    for (int t = 0; t < TT; t++) {
        // prefetch next-step inputs into regs (overlaps MMA phase)
        int tn = (t + 1 < TT) ? t + 1 : t;
        float act_n = g_act[tn * 512 + tid];
        float s_n = (tid < 4) ? g_x[tn * 512 + n0 + tid] : 0.0f;

        // ---- gate GEMM: D[j 32][n 8] per warp, K=128 over 8 ktiles ----
        float acc0[4] = {0, 0, 0, 0};
        float acc1[4] = {0, 0, 0, 0};
#pragma unroll
        for (int kt = 0; kt < 8; kt++) {
            int ka = kt * 16 + tg * 2;
            uint32_t bh0 = *(const uint32_t*)&hhi[g * 136 + ka];
            uint32_t bh1 = *(const uint32_t*)&hhi[g * 136 + ka + 8];
            uint32_t bl0 = *(const uint32_t*)&hlo[g * 136 + ka];
            uint32_t bl1 = *(const uint32_t*)&hlo[g * 136 + ka + 8];
            {
                uint4 wv = whi[kt];
                uint32_t a[4] = {wv.x, wv.y, wv.z, wv.w};
                mma_bf16(acc0, a, bh0, bh1);
                mma_bf16(acc0, a, bl0, bl1);
                uint4 wl = wlo_s[((w * 2 + 0) * 8 + kt) * 32 + lane];
                uint32_t al[4] = {wl.x, wl.y, wl.z, wl.w};
                mma_bf16(acc0, al, bh0, bh1);
            }
            {
                uint4 wv = whi[8 + kt];
                uint32_t a[4] = {wv.x, wv.y, wv.z, wv.w};
                mma_bf16(acc1, a, bh0, bh1);
                mma_bf16(acc1, a, bl0, bl1);
                uint4 wl = wlo_s[((w * 2 + 1) * 8 + kt) * 32 + lane];
                uint32_t al[4] = {wl.x, wl.y, wl.z, wl.w};
                mma_bf16(acc1, al, bh0, bh1);
            }
        }
        if (tg < 2) {
            int j0 = w * 32 + g;
            gt_s[(tg * 2) * GTP + j0]          = acc0[0];
            gt_s[(tg * 2 + 1) * GTP + j0]      = acc0[1];
            gt_s[(tg * 2) * GTP + j0 + 8]      = acc0[2];
            gt_s[(tg * 2 + 1) * GTP + j0 + 8]  = acc0[3];
            int j1 = j0 + 16;
            gt_s[(tg * 2) * GTP + j1]          = acc1[0];
            gt_s[(tg * 2 + 1) * GTP + j1]      = acc1[1];
            gt_s[(tg * 2) * GTP + j1 + 8]      = acc1[2];
            gt_s[(tg * 2 + 1) * GTP + j1 + 8]  = acc1[3];
        }
        act_s[((t + 1) & 1) * 512 + tid] = act_n;
        if (tid < 4) s_s[((t + 1) & 1) * 4 + tid] = s_n;
        __syncthreads();

        // ---- pointwise: thread = (pn, pj); torch gate order i,f,g,o ----
        {
            const float* ab = act_s + (t & 1) * 512;
            float sv = s_s[(t & 1) * 4 + pn];
            float gv[4];
#pragma unroll
            for (int e = 0; e < 4; e++) {
                int gi = e * 128 + pj;
                gv[e] = gt_s[pn * GTP + gi] + ab[gi] + sv * wih_s[gi];
            }
            float c = fsig(gv[1]) * c_r + fsig(gv[0]) * ftanh(gv[2]);
            float h = fsig(gv[3]) * ftanh(c);
            c_r = c;
            __nv_bfloat16 hb = __float2bfloat16(h);
            __nv_bfloat16 lb = __float2bfloat16(h - __bfloat162float(hb));
            hhi[pn * 136 + pj] = hb;
            hlo[pn * 136 + pj] = lb;
            g_Kh[(size_t)t * 65536 + w_off] = hb;
            g_Kl[(size_t)t * 65536 + w_off] = lb;
        }
        __syncthreads();
    }
}

// ---------------------------------------------------------------------------
// Attention via mma.sync with FRAGMENT-LINEAR smem (conflict-free LDS.128/.64).
// CTA = 64 m x 512 i, 4 chunks of 128 i. smem ~99KB -> 2 CTAs/SM.
// per kk per warp: 2 LDS.128 (A) + 8 LDS.64 (B) + 12 HMMA.
// ---------------------------------------------------------------------------
#define QFH_B 0
#define QFL_B 16384
#define KFH_B 32768
#define KFL_B 65536
#define SX_B  98304
#define PART_B 100352
#define ATTN_SMEM (PART_B + 1024)

__global__ __launch_bounds__(512) void attn_kernel(float* __restrict__ out) {
    extern __shared__ char smc[];
    __nv_bfloat16* qfh = (__nv_bfloat16*)(smc + QFH_B);  // 8192 : 32 A-tiles
    __nv_bfloat16* qfl = (__nv_bfloat16*)(smc + QFL_B);
    __nv_bfloat16* kfh = (__nv_bfloat16*)(smc + KFH_B);  // 16384 : 128 B-tiles
    __nv_bfloat16* kfl = (__nv_bfloat16*)(smc + KFL_B);
    float* s_s  = (float*)(smc + SX_B);                  // 512 floats
    float* part = (float*)(smc + PART_B);                // 256 floats

    int tid = threadIdx.x;
    int warp = tid >> 5;
    int lane = tid & 31;
    int wband = warp >> 2;   // 0..3 : m band (16 rows = 1 A-tile row)
    int iq    = warp & 3;    // 0..3 : i quarter (32 i = 4 B-tiles)
    int g  = lane >> 2;      // 0..7
    int tg = lane & 3;       // 0..3
    int m0 = wband * 16;
    int mq = blockIdx.x;     // 0..15 (64 m rows each)
    int t  = blockIdx.y;     // 0..255

    float c0 = g_c[mq * 64 + m0 + g];
    float c1 = g_c[mq * 64 + m0 + g + 8];

    // stage q' fragment image (32 tiles, contiguous 16KB per half) + s
    {
        const float4* sh = (const float4*)&g_qh[(size_t)mq * 8192];
        const float4* sl = (const float4*)&g_ql[(size_t)mq * 8192];
        float4* dh = (float4*)qfh;
        float4* dl = (float4*)qfl;
#pragma unroll
        for (int f = 0; f < 2; f++) {
            dh[tid + f * 512] = sh[tid + f * 512];
            dl[tid + f * 512] = sl[tid + f * 512];
        }
        const float4* sx = (const float4*)&g_x[t * 512];
        if (tid < 128) ((float4*)s_s)[tid] = sx[tid];
    }

    float pr0 = 0.0f, pr1 = 0.0f;
    const float inv = 0.0883883476483184f;  // 1/sqrt(128)

#pragma unroll 1
    for (int c = 0; c < 4; c++) {
        if (c > 0) __syncthreads();
        {
            // chunk c = B-tiles [c*128, c*128+128) : contiguous 32KB per half
            const float4* sh = (const float4*)&g_Kh[(size_t)t * 65536 + (size_t)c * 16384];
            const float4* sl = (const float4*)&g_Kl[(size_t)t * 65536 + (size_t)c * 16384];
            float4* dh = (float4*)kfh;
            float4* dl = (float4*)kfl;
#pragma unroll
            for (int f = 0; f < 4; f++) {
                dh[tid + f * 512] = sh[tid + f * 512];
                dl[tid + f * 512] = sl[tid + f * 512];
            }
        }
        __syncthreads();

        float acc[4][4];
#pragma unroll
        for (int nt = 0; nt < 4; nt++)
#pragma unroll
            for (int e = 0; e < 4; e++) acc[nt][e] = 0.0f;

#pragma unroll 1
        for (int kk = 0; kk < 8; kk++) {
            uint4 AH = *(const uint4*)&qfh[((wband * 8 + kk) << 8) + lane * 8];
            uint4 AL = *(const uint4*)&qfl[((wband * 8 + kk) << 8) + lane * 8];
            uint32_t ah[4] = {AH.x, AH.y, AH.z, AH.w};
            uint32_t al[4] = {AL.x, AL.y, AL.z, AL.w};
#pragma unroll
            for (int nt = 0; nt < 4; nt++) {
                int tb = (((iq * 4 + nt) * 8 + kk) << 7) + lane * 4;
                uint2 BH = *(const uint2*)&kfh[tb];
                uint2 BL = *(const uint2*)&kfl[tb];
                mma_bf16(acc[nt], ah, BH.x, BH.y);   // hi*hi
                mma_bf16(acc[nt], ah, BL.x, BL.y);   // hi*lo
                mma_bf16(acc[nt], al, BH.x, BH.y);   // lo*hi
            }
        }

        // epilogue: tanh((score + c[m]) * inv) * s[i]
#pragma unroll
        for (int nt = 0; nt < 4; nt++) {
            int i0 = c * 128 + iq * 32 + nt * 8 + tg * 2;
            float sv0 = s_s[i0], sv1 = s_s[i0 + 1];
            pr0 = fmaf(ftanh((acc[nt][0] + c0) * inv), sv0, pr0);
            pr0 = fmaf(ftanh((acc[nt][1] + c0) * inv), sv1, pr0);
            pr1 = fmaf(ftanh((acc[nt][2] + c1) * inv), sv0, pr1);
            pr1 = fmaf(ftanh((acc[nt][3] + c1) * inv), sv1, pr1);
        }
    }

    pr0 += __shfl_xor_sync(0xffffffffu, pr0, 1);
    pr0 += __shfl_xor_sync(0xffffffffu, pr0, 2);
    pr1 += __shfl_xor_sync(0xffffffffu, pr1, 1);
    pr1 += __shfl_xor_sync(0xffffffffu, pr1, 2);
    if (tg == 0) {
        part[iq * 64 + m0 + g]     = pr0;
        part[iq * 64 + m0 + g + 8] = pr1;
    }
    __syncthreads();
    if (tid < 64)
        out[t * 1024 + mq * 64 + tid] =
            ftanh(part[tid] + part[64 + tid] + part[128 + tid] + part[192 + tid]);
}

// ---------------------------------------------------------------------------
extern "C" void kernel_launch(void* const* d_in, const int* in_sizes, int n_in,
                              void* d_out, int out_size) {
    const float* obs      = (const float*)d_in[0];
    const float* prev_act = (const float*)d_in[1];
    const float* in_shift = (const float*)d_in[2];
    const float* in_scale = (const float*)d_in[3];
    const float* pe       = (const float*)d_in[4];
    const float* W_ih     = (const float*)d_in[5];
    const float* b_ih     = (const float*)d_in[6];
    const float* W_hh     = (const float*)d_in[7];
    const float* b_hh     = (const float*)d_in[8];
    const float* Wq       = (const float*)d_in[9];
    const float* bq       = (const float*)d_in[10];
    const float* Wk       = (const float*)d_in[11];
    const float* bk       = (const float*)d_in[12];
    float* out = (float*)d_out;

    cudaFuncSetAttribute(attn_kernel, cudaFuncAttributeMaxDynamicSharedMemorySize,
                         ATTN_SMEM);
    cudaFuncSetAttribute(lstm_kernel, cudaFuncAttributeMaxDynamicSharedMemorySize,
                         LSTM_SMEM);

    prep_kernel<<<512, 256>>>(obs, prev_act, in_shift, in_scale, W_ih, b_ih, b_hh);
    wfrag_kernel<<<32, 256>>>(W_hh);
    q1_kernel<<<512, 256>>>(pe, Wq, bq);
    q2_kernel<<<512, 256>>>(Wk, bk);
    lstm_kernel<<<128, 512, LSTM_SMEM>>>();
    dim3 ga(16, 256);
    attn_kernel<<<ga, 512, ATTN_SMEM>>>(out);
}